// round 16
// baseline (speedup 1.0000x reference)
#include <cuda_runtime.h>
#include <cuda_bf16.h>
#include <cstdint>
#include <cstddef>

#define N_NODES 100000
#define M_PAD   100096
#define N_EDGES 300000
#define N_GRAPHS 2048

// ---------------- scratch (no allocations allowed) ----------------
__device__ __align__(256) float g_h[(size_t)N_NODES * 512];
__device__ __align__(256) uint32_t g_zp[(size_t)M_PAD * 256];   // packed z (hi/lo)
__device__ __align__(256) uint32_t g_tp[(size_t)M_PAD * 512];   // packed t (hi/lo)
__device__ __align__(256) __nv_bfloat16 g_whi[622592];
__device__ __align__(256) __nv_bfloat16 g_wlo[622592];
// CSR scratch
__device__ int g_counts[N_NODES];
__device__ int g_off[N_NODES];
__device__ int g_cur[N_NODES];
__device__ int g_bsum[512];
__device__ int g_esrc[N_EDGES];

// packed A layout: element (r, c) of [M, K]:
//   byte r*K*4 + (c>>3)*32 + (c&7)*2 (hi);  +16 (lo)

// ---------------- helpers ----------------
__device__ __forceinline__ uint32_t smem_u32(const void* p) {
    uint32_t a;
    asm("{ .reg .u64 t; cvta.to.shared.u64 t, %1; cvt.u32.u64 %0, t; }"
        : "=r"(a) : "l"(p));
    return a;
}

#define LDM4(r, addr)                                                         \
    asm volatile("ldmatrix.sync.aligned.m8n8.x4.shared.b16 {%0,%1,%2,%3}, [%4];" \
                 : "=r"((r)[0]), "=r"((r)[1]), "=r"((r)[2]), "=r"((r)[3])     \
                 : "r"(addr))

#define MMA16816(c, a, b0, b1)                                                \
    asm volatile("mma.sync.aligned.m16n8k16.row.col.f32.bf16.bf16.f32 "        \
                 "{%0,%1,%2,%3}, {%4,%5,%6,%7}, {%8,%9}, {%0,%1,%2,%3};"       \
                 : "+f"((c)[0]), "+f"((c)[1]), "+f"((c)[2]), "+f"((c)[3])      \
                 : "r"((a)[0]), "r"((a)[1]), "r"((a)[2]), "r"((a)[3]),         \
                   "r"(b0), "r"(b1))

#define CP16(saddr, gaddr)                                                    \
    asm volatile("cp.async.cg.shared.global [%0], [%1], 16;" ::               \
                 "r"(saddr), "l"(gaddr))

#define SWZ(row, c16) ((uint32_t)((row) * 64 + ((((c16) ^ (((row) >> 1) & 3))) << 4)))

__device__ __forceinline__ void split2(float a, float b, uint32_t& hw, uint32_t& lw) {
    __nv_bfloat162 hp = __floats2bfloat162_rn(a, b);
    float2 hf = __bfloat1622float2(hp);
    __nv_bfloat162 lp = __floats2bfloat162_rn(a - hf.x, b - hf.y);
    hw = *reinterpret_cast<uint32_t*>(&hp);
    lw = *reinterpret_cast<uint32_t*>(&lp);
}

// ---------------- fused: weight prep + embed + zero counts ----------------
#define PREP_BLKS 2432
#define EMB_BLKS  3125
#define ZERO_BLKS 391

__global__ __launch_bounds__(256)
void fused_prep(const float* __restrict__ w0, const float* __restrict__ w1,
                const float* __restrict__ w2, const float* __restrict__ w3,
                const float* __restrict__ w4, const float* __restrict__ w5,
                __nv_bfloat16* __restrict__ hi, __nv_bfloat16* __restrict__ lo,
                const float* __restrict__ x, const float* __restrict__ We,
                const float* __restrict__ be, float* __restrict__ h,
                int* __restrict__ counts) {
    int bid = blockIdx.x;
    int tid = threadIdx.x;
    if (bid < PREP_BLKS) {
        int i = bid * 256 + tid;
        if (i >= 622592) return;
        const float* W;
        int off, K, N;
        if (i < 32768)       { W = w0; off = 0;      K = 128; N = 256; }
        else if (i < 98304)  { W = w1; off = 32768;  K = 256; N = 256; }
        else if (i < 163840) { W = w2; off = 98304;  K = 256; N = 256; }
        else if (i < 229376) { W = w3; off = 163840; K = 256; N = 256; }
        else if (i < 360448) { W = w4; off = 229376; K = 256; N = 512; }
        else                 { W = w5; off = 360448; K = 512; N = 512; }
        int j = i - off;
        int k = j / N, n = j % N;
        float v = W[j];
        __nv_bfloat16 hh = __float2bfloat16(v);
        float r = v - __bfloat162float(hh);
        hi[(size_t)off + (size_t)n * K + k] = hh;
        lo[(size_t)off + (size_t)n * K + k] = __float2bfloat16(r);
    } else if (bid < PREP_BLKS + EMB_BLKS) {
        __shared__ float Ws[40 * 128];
        __shared__ float xs[32 * 40];
        __shared__ float bs[128];
        int n0 = (bid - PREP_BLKS) * 32;
        for (int i = tid; i < 40 * 128; i += 256) Ws[i] = We[i];
        if (tid < 128) bs[tid] = be[tid];
        for (int i = tid; i < 32 * 40; i += 256) {
            int n = n0 + (i / 40);
            xs[i] = (n < N_NODES) ? x[(size_t)n * 40 + (i % 40)] : 0.f;
        }
        __syncthreads();
        for (int i = tid; i < 32 * 128; i += 256) {
            int nl = i >> 7, col = i & 127;
            int n = n0 + nl;
            if (n >= N_NODES) continue;
            float acc = bs[col];
#pragma unroll
            for (int k = 0; k < 40; k++)
                acc = fmaf(xs[nl * 40 + k], Ws[k * 128 + col], acc);
            h[(size_t)n * 128 + col] = acc;
        }
    } else {
        int i = (bid - PREP_BLKS - EMB_BLKS) * 256 + tid;
        if (i < N_NODES) counts[i] = 0;
    }
}

// ---------------- CSR build ----------------
__global__ void hist_kernel(const int* __restrict__ ei, int* __restrict__ counts) {
    int e = blockIdx.x * blockDim.x + threadIdx.x;
    if (e >= N_EDGES) return;
    atomicAdd(&counts[ei[N_EDGES + e]], 1);
}

__global__ void scan1_kernel(const int* __restrict__ counts, int* __restrict__ off,
                             int* __restrict__ bsum) {
    int t = threadIdx.x;
    int idx = blockIdx.x * 256 + t;
    int c = (idx < N_NODES) ? counts[idx] : 0;
    int v = c;
#pragma unroll
    for (int o = 1; o < 32; o <<= 1) {
        int u = __shfl_up_sync(0xffffffffu, v, o);
        if ((t & 31) >= o) v += u;
    }
    __shared__ int ws[8];
    if ((t & 31) == 31) ws[t >> 5] = v;
    __syncthreads();
    if (t < 8) {
        int wv = ws[t];
#pragma unroll
        for (int o = 1; o < 8; o <<= 1) {
            int u = __shfl_up_sync(0xffu, wv, o);
            if (t >= o) wv += u;
        }
        ws[t] = wv;
    }
    __syncthreads();
    int base = (t >= 32) ? ws[(t >> 5) - 1] : 0;
    int inc = v + base;
    if (idx < N_NODES) off[idx] = inc - c;
    if (t == 255) bsum[blockIdx.x] = inc;
}

__global__ void scan2_kernel(int* __restrict__ off, const int* __restrict__ bsum,
                             int* __restrict__ cursor, int nblk) {
    __shared__ int sp[256];
    int t = threadIdx.x;
    int s = 0;
    for (int j = t; j < nblk; j += 256)
        if (j < (int)blockIdx.x) s += bsum[j];
    sp[t] = s;
    __syncthreads();
#pragma unroll
    for (int o = 128; o > 0; o >>= 1) {
        if (t < o) sp[t] += sp[t + o];
        __syncthreads();
    }
    int prefix = sp[0];
    int idx = blockIdx.x * 256 + t;
    if (idx < N_NODES) {
        int v = off[idx] + prefix;
        off[idx] = v;
        cursor[idx] = v;
    }
}

__global__ void fill_kernel(const int* __restrict__ ei, int* __restrict__ cursor,
                            int* __restrict__ esrc) {
    int e = blockIdx.x * blockDim.x + threadIdx.x;
    if (e >= N_EDGES) return;
    int s = ei[e];
    int d = ei[N_EDGES + e];
    int slot = atomicAdd(&cursor[d], 1);
    esrc[slot] = s;
}

// ---------------- agg + pack: z = (1+eps)*h[n] + sum h[src], packed hi/lo ----
template <int LPN>
__global__ __launch_bounds__(256)
void agg_pack(const int* __restrict__ off, const int* __restrict__ cur,
              const int* __restrict__ esrc, const float* __restrict__ h,
              const float* __restrict__ eps, int l, uint4* __restrict__ zp) {
    const int D = LPN * 8;
    int nid = blockIdx.x * (256 / LPN) + threadIdx.x / LPN;
    int gl = threadIdx.x % LPN;
    if (nid >= N_NODES) return;
    float sc = 1.f + eps[l];
    const float4* hp = (const float4*)(h + (size_t)nid * D) + gl * 2;
    float4 a = hp[0], b = hp[1];
    a.x *= sc; a.y *= sc; a.z *= sc; a.w *= sc;
    b.x *= sc; b.y *= sc; b.z *= sc; b.w *= sc;
    int s = off[nid], e = cur[nid];
    int r = (s < e) ? esrc[s] : 0;
    for (int i = s; i < e; i++) {
        int rn = (i + 1 < e) ? esrc[i + 1] : 0;
        const float4* q = (const float4*)(h + (size_t)r * D) + gl * 2;
        float4 u = q[0], v = q[1];
        r = rn;
        a.x += u.x; a.y += u.y; a.z += u.z; a.w += u.w;
        b.x += v.x; b.y += v.y; b.z += v.z; b.w += v.w;
    }
    uint4 hi, lo;
    split2(a.x, a.y, hi.x, lo.x);
    split2(a.z, a.w, hi.y, lo.y);
    split2(b.x, b.y, hi.z, lo.z);
    split2(b.z, b.w, hi.w, lo.w);
    size_t base = (size_t)nid * (D / 4) + gl * 2;
    __stcs(&zp[base], hi);
    __stcs(&zp[base + 1], lo);
}

// ---------------- HMMA bf16x3 GEMM, persistent CTAs ----------------
// BM=128, BN=128, BK=32, 128 threads, 2x2 warps, warp tile 64x64, 3-stage,
// 2 CTAs/SM, grid=296 persistent; tiles looped tx-fastest (B stays L2-hot).
#define STG_A 0
#define STG_B_HI 16384
#define STG_B_LO 24576
#define STG_SIZE 32768
#define GEMM_SMEM (3 * STG_SIZE)
#define GEMM_GRID 296

template <int OMODE>   // 0: C fp32; 1: Cp packed hi/lo
__global__ __launch_bounds__(128, 2)
void mma_gemm(const char* __restrict__ Ab, const __nv_bfloat16* __restrict__ Bhi,
              const __nv_bfloat16* __restrict__ Blo, const float* __restrict__ bias,
              float* __restrict__ C, char* __restrict__ Cp,
              int M, int K, int N, int relu, int ntx, int ntiles) {
    extern __shared__ char smem[];
    const int tid = threadIdx.x;
    const int lane = tid & 31;
    const int w = tid >> 5;              // 0..3
    const int wm = w & 1, wn = w >> 1;   // 2 x 2 warp grid, tile 64x64
    const uint32_t sbase = smem_u32(smem);
    const int S = K >> 5;

    // per-lane ldmatrix bases (tile-invariant)
    uint32_t a_row128[4], a_rkey[4];
#pragma unroll
    for (int mt = 0; mt < 4; mt++) {
        int row = wm * 64 + mt * 16 + (lane & 15);
        a_row128[mt] = (uint32_t)(row * 128);
        a_rkey[mt] = (uint32_t)(row & 7);
    }
    const uint32_t a_kbit = (lane >> 4) & 1;
    uint32_t b_base[4], b_key[4];
#pragma unroll
    for (int np = 0; np < 4; np++) {
        int row = wn * 64 + np * 16 + ((lane >> 4) & 1) * 8 + (lane & 7);
        b_base[np] = (uint32_t)(row * 64);
        b_key[np] = (uint32_t)((row >> 1) & 3);
    }
    const uint32_t b_c16_bit = (lane >> 3) & 1;

#define CP_STAGE(st, k0)                                                      \
    {                                                                         \
        uint32_t sa_ = sbase + (st) * STG_SIZE + STG_A;                       \
        uint32_t sb_ = sbase + (st) * STG_SIZE;                               \
        _Pragma("unroll")                                                     \
        for (int j_ = 0; j_ < 8; j_++) {                                      \
            int idx_ = tid + j_ * 128;                                        \
            int rr_ = idx_ >> 3, q_ = idx_ & 7;                               \
            size_t go_ = (size_t)(bm + rr_) * K * 4 + (size_t)(k0) * 4 +      \
                         (q_ >> 1) * 32 + (q_ & 1) * 16;                      \
            uint32_t so_ = (uint32_t)(rr_ * 128 + ((q_ ^ (rr_ & 7)) << 4));   \
            CP16(sa_ + so_, Ab + go_);                                        \
        }                                                                     \
        _Pragma("unroll")                                                     \
        for (int j_ = 0; j_ < 4; j_++) {                                      \
            int idx_ = tid + j_ * 128;                                        \
            int n_ = idx_ >> 2, g_ = idx_ & 3;                                \
            size_t go_ = (size_t)(bn + n_) * K + (k0) + g_ * 8;               \
            uint32_t so_ = SWZ(n_, g_);                                       \
            CP16(sb_ + STG_B_HI + so_, Bhi + go_);                            \
            CP16(sb_ + STG_B_LO + so_, Blo + go_);                            \
        }                                                                     \
        asm volatile("cp.async.commit_group;" ::: "memory");                  \
    }

    for (int tile = blockIdx.x; tile < ntiles; tile += GEMM_GRID) {
        const int bm = (tile / ntx) * 128;
        const int bn = (tile % ntx) * 128;

        __syncthreads();   // retire previous tile's smem reads before refill

        float acc[4][8][4];
#pragma unroll
        for (int i = 0; i < 4; i++)
#pragma unroll
            for (int j = 0; j < 8; j++)
#pragma unroll
                for (int q = 0; q < 4; q++) acc[i][j][q] = 0.f;

        CP_STAGE(0, 0);
        CP_STAGE(1, 32);
        asm volatile("cp.async.wait_group 1;" ::: "memory");
        __syncthreads();

        int cst = 0;
        for (int s = 0; s < S; s++) {
            if (s + 2 < S) CP_STAGE((s + 2) % 3, (s + 2) << 5);

            const uint32_t sg = sbase + cst * STG_SIZE;
#pragma unroll
            for (int kh = 0; kh < 2; kh++) {
                uint32_t ahi[4][4], alo[4][4];
#pragma unroll
                for (int mt = 0; mt < 4; mt++) {
                    uint32_t q = (uint32_t)(kh * 2 + a_kbit) * 2;
                    uint32_t base = sg + STG_A + a_row128[mt];
                    LDM4(ahi[mt], base + ((q ^ a_rkey[mt]) << 4));
                    LDM4(alo[mt], base + (((q + 1) ^ a_rkey[mt]) << 4));
                }
#pragma unroll
                for (int np = 0; np < 4; np++) {
                    uint32_t c16 = (uint32_t)(kh * 2) + b_c16_bit;
                    uint32_t bd = sg + b_base[np] + ((c16 ^ b_key[np]) << 4);
                    uint32_t bh[4], bl[4];
                    LDM4(bh, bd + STG_B_HI);
                    LDM4(bl, bd + STG_B_LO);
#pragma unroll
                    for (int mt = 0; mt < 4; mt++) {
                        MMA16816(acc[mt][np * 2], ahi[mt], bh[0], bh[1]);
                        MMA16816(acc[mt][np * 2], ahi[mt], bl[0], bl[1]);
                        MMA16816(acc[mt][np * 2], alo[mt], bh[0], bh[1]);
                        MMA16816(acc[mt][np * 2 + 1], ahi[mt], bh[2], bh[3]);
                        MMA16816(acc[mt][np * 2 + 1], ahi[mt], bl[2], bl[3]);
                        MMA16816(acc[mt][np * 2 + 1], alo[mt], bh[2], bh[3]);
                    }
                }
            }

            if (s + 1 < S) {
                if (s + 2 < S) {
                    asm volatile("cp.async.wait_group 1;" ::: "memory");
                } else {
                    asm volatile("cp.async.wait_group 0;" ::: "memory");
                }
                __syncthreads();
                cst = (s + 1) % 3;
            }
        }

        // ---- epilogue ----
#pragma unroll
        for (int mt = 0; mt < 4; mt++) {
            int r0 = bm + wm * 64 + mt * 16 + (lane >> 2);
#pragma unroll
            for (int nt = 0; nt < 8; nt++) {
                int col = bn + wn * 64 + nt * 8 + (lane & 3) * 2;
                float b0 = bias[col], b1 = bias[col + 1];
                float v0 = acc[mt][nt][0] + b0, v1 = acc[mt][nt][1] + b1;
                float v2 = acc[mt][nt][2] + b0, v3 = acc[mt][nt][3] + b1;
                if (relu) {
                    v0 = fmaxf(v0, 0.f); v1 = fmaxf(v1, 0.f);
                    v2 = fmaxf(v2, 0.f); v3 = fmaxf(v3, 0.f);
                }
                if (OMODE == 0) {
                    if (r0 < M) *(float2*)(C + (size_t)r0 * N + col) = make_float2(v0, v1);
                    if (r0 + 8 < M) *(float2*)(C + (size_t)(r0 + 8) * N + col) = make_float2(v2, v3);
                } else {
                    uint32_t h01, l01, h23, l23;
                    split2(v0, v1, h01, l01);
                    split2(v2, v3, h23, l23);
                    size_t base = (size_t)r0 * N * 4 + (size_t)(col >> 3) * 32 +
                                  (col & 7) * 2;
                    if (r0 < M) {
                        *(uint32_t*)(Cp + base) = h01;
                        *(uint32_t*)(Cp + base + 16) = l01;
                    }
                    if (r0 + 8 < M) {
                        size_t b2_ = base + (size_t)8 * N * 4;
                        *(uint32_t*)(Cp + b2_) = h23;
                        *(uint32_t*)(Cp + b2_ + 16) = l23;
                    }
                }
            }
        }
    }
#undef CP_STAGE
}

// ---------------- fused pool + task head (batch is sorted) ----------------
__device__ __forceinline__ int lowb(const int* __restrict__ a, int n, int v) {
    int lo = 0, hi = n;
    while (lo < hi) {
        int m = (lo + hi) >> 1;
        if (a[m] < v) lo = m + 1; else hi = m;
    }
    return lo;
}

__global__ __launch_bounds__(128)
void pool_task_kernel(const int* __restrict__ batch, const float* __restrict__ h,
                      const float* __restrict__ W, const float* __restrict__ b,
                      float* __restrict__ out) {
    int g = blockIdx.x;
    int t = threadIdx.x;
    int start = lowb(batch, N_NODES, g);
    int end = lowb(batch, N_NODES, g + 1);
    float4 acc = make_float4(0.f, 0.f, 0.f, 0.f);
    for (int n = start; n < end; n++) {
        float4 v = ((const float4*)(h + (size_t)n * 512))[t];
        acc.x += v.x; acc.y += v.y; acc.z += v.z; acc.w += v.w;
    }
    float4 wv = ((const float4*)W)[t];
    float d = acc.x * wv.x + acc.y * wv.y + acc.z * wv.z + acc.w * wv.w;
#pragma unroll
    for (int o = 16; o > 0; o >>= 1) d += __shfl_xor_sync(0xffffffffu, d, o);
    __shared__ float s[4];
    if ((t & 31) == 0) s[t >> 5] = d;
    __syncthreads();
    if (t == 0) out[g] = s[0] + s[1] + s[2] + s[3] + b[0];
}

// ---------------- launch ----------------
extern "C" void kernel_launch(void* const* d_in, const int* in_sizes, int n_in,
                              void* d_out, int out_size) {
    const float* x       = (const float*)d_in[0];
    const int*   ei      = (const int*)d_in[1];
    const int*   batch   = (const int*)d_in[2];
    const float* W_embed = (const float*)d_in[3];
    const float* b_embed = (const float*)d_in[4];
    const float* eps     = (const float*)d_in[5];
    const float* W1[3] = {(const float*)d_in[6],  (const float*)d_in[10], (const float*)d_in[14]};
    const float* b1[3] = {(const float*)d_in[7],  (const float*)d_in[11], (const float*)d_in[15]};
    const float* W2[3] = {(const float*)d_in[8],  (const float*)d_in[12], (const float*)d_in[16]};
    const float* b2[3] = {(const float*)d_in[9],  (const float*)d_in[13], (const float*)d_in[17]};
    const float* W_task = (const float*)d_in[18];
    const float* b_task = (const float*)d_in[19];
    float* out = (float*)d_out;

    float *h;
    uint32_t *zp, *tp;
    __nv_bfloat16 *whi, *wlo;
    int *counts, *off, *cur, *bsum, *esrc;
    cudaGetSymbolAddress((void**)&h, g_h);
    cudaGetSymbolAddress((void**)&zp, g_zp);
    cudaGetSymbolAddress((void**)&tp, g_tp);
    cudaGetSymbolAddress((void**)&whi, g_whi);
    cudaGetSymbolAddress((void**)&wlo, g_wlo);
    cudaGetSymbolAddress((void**)&counts, g_counts);
    cudaGetSymbolAddress((void**)&off, g_off);
    cudaGetSymbolAddress((void**)&cur, g_cur);
    cudaGetSymbolAddress((void**)&bsum, g_bsum);
    cudaGetSymbolAddress((void**)&esrc, g_esrc);

    cudaFuncSetAttribute(mma_gemm<0>, cudaFuncAttributeMaxDynamicSharedMemorySize, GEMM_SMEM);
    cudaFuncSetAttribute(mma_gemm<1>, cudaFuncAttributeMaxDynamicSharedMemorySize, GEMM_SMEM);

    fused_prep<<<PREP_BLKS + EMB_BLKS + ZERO_BLKS, 256>>>(
        W1[0], W2[0], W1[1], W2[1], W1[2], W2[2], whi, wlo,
        x, W_embed, b_embed, h, counts);

    const int NBLK = (N_NODES + 255) / 256;   // 391
    hist_kernel<<<(N_EDGES + 255) / 256, 256>>>(ei, counts);
    scan1_kernel<<<NBLK, 256>>>(counts, off, bsum);
    scan2_kernel<<<NBLK, 256>>>(off, bsum, cur, NBLK);
    fill_kernel<<<(N_EDGES + 255) / 256, 256>>>(ei, cur, esrc);

    const size_t woff[6] = {0, 32768, 98304, 163840, 229376, 360448};
    const int Din[3]  = {128, 256, 256};
    const int Dmid[3] = {256, 256, 512};
    const int Dout[3] = {256, 256, 512};
    const int MT = M_PAD / 128;   // 782

    for (int l = 0; l < 3; l++) {
        int D = Din[l];

        if (D == 128)
            agg_pack<16><<<(N_NODES + 15) / 16, 256>>>(off, cur, esrc, h, eps, l,
                                                       (uint4*)zp);
        else
            agg_pack<32><<<(N_NODES + 7) / 8, 256>>>(off, cur, esrc, h, eps, l,
                                                     (uint4*)zp);

        // GEMM1: packed z -> packed t, relu (persistent grid)
        {
            int ntx = Dmid[l] / 128;
            mma_gemm<1><<<GEMM_GRID, 128, GEMM_SMEM>>>(
                (const char*)zp, whi + woff[2 * l], wlo + woff[2 * l], b1[l],
                nullptr, (char*)tp, N_NODES, D, Dmid[l], 1, ntx, ntx * MT);
        }

        // GEMM2: packed t -> h fp32, relu unless last (persistent grid)
        {
            int ntx = Dout[l] / 128;
            mma_gemm<0><<<GEMM_GRID, 128, GEMM_SMEM>>>(
                (const char*)tp, whi + woff[2 * l + 1], wlo + woff[2 * l + 1], b2[l],
                h, nullptr, N_NODES, Dmid[l], Dout[l], (l < 2) ? 1 : 0,
                ntx, ntx * MT);
        }
    }

    pool_task_kernel<<<N_GRAPHS, 128>>>(batch, h, W_task, b_task, out);
}

// round 17
// speedup vs baseline: 1.1022x; 1.1022x over previous
#include <cuda_runtime.h>
#include <cuda_bf16.h>
#include <cstdint>
#include <cstddef>

#define N_NODES 100000
#define M_PAD   100096
#define N_EDGES 300000
#define N_GRAPHS 2048

// ---------------- scratch (no allocations allowed) ----------------
__device__ __align__(256) float g_h[(size_t)N_NODES * 512];
__device__ __align__(256) uint32_t g_zp[(size_t)M_PAD * 256];   // packed z (hi/lo)
__device__ __align__(256) uint32_t g_tp[(size_t)M_PAD * 512];   // packed t (hi/lo)
__device__ __align__(256) __nv_bfloat16 g_whi[622592];
__device__ __align__(256) __nv_bfloat16 g_wlo[622592];
// CSR scratch
__device__ int g_counts[N_NODES];
__device__ int g_off[N_NODES];
__device__ int g_cur[N_NODES];
__device__ int g_bsum[512];
__device__ int g_esrc[N_EDGES];

// packed A layout: element (r, c) of [M, K]:
//   byte r*K*4 + (c>>3)*32 + (c&7)*2 (hi);  +16 (lo)

// ---------------- helpers ----------------
__device__ __forceinline__ uint32_t smem_u32(const void* p) {
    uint32_t a;
    asm("{ .reg .u64 t; cvta.to.shared.u64 t, %1; cvt.u32.u64 %0, t; }"
        : "=r"(a) : "l"(p));
    return a;
}

#define LDM4(r, addr)                                                         \
    asm volatile("ldmatrix.sync.aligned.m8n8.x4.shared.b16 {%0,%1,%2,%3}, [%4];" \
                 : "=r"((r)[0]), "=r"((r)[1]), "=r"((r)[2]), "=r"((r)[3])     \
                 : "r"(addr))

#define MMA16816(c, a, b0, b1)                                                \
    asm volatile("mma.sync.aligned.m16n8k16.row.col.f32.bf16.bf16.f32 "        \
                 "{%0,%1,%2,%3}, {%4,%5,%6,%7}, {%8,%9}, {%0,%1,%2,%3};"       \
                 : "+f"((c)[0]), "+f"((c)[1]), "+f"((c)[2]), "+f"((c)[3])      \
                 : "r"((a)[0]), "r"((a)[1]), "r"((a)[2]), "r"((a)[3]),         \
                   "r"(b0), "r"(b1))

#define CP16(saddr, gaddr)                                                    \
    asm volatile("cp.async.cg.shared.global [%0], [%1], 16;" ::               \
                 "r"(saddr), "l"(gaddr))

#define SWZ(row, c16) ((uint32_t)((row) * 64 + ((((c16) ^ (((row) >> 1) & 3))) << 4)))

__device__ __forceinline__ void split2(float a, float b, uint32_t& hw, uint32_t& lw) {
    __nv_bfloat162 hp = __floats2bfloat162_rn(a, b);
    float2 hf = __bfloat1622float2(hp);
    __nv_bfloat162 lp = __floats2bfloat162_rn(a - hf.x, b - hf.y);
    hw = *reinterpret_cast<uint32_t*>(&hp);
    lw = *reinterpret_cast<uint32_t*>(&lp);
}

// ---------------- fused: weight prep + embed + zero counts ----------------
#define PREP_BLKS 2432
#define EMB_BLKS  3125
#define ZERO_BLKS 391

__global__ __launch_bounds__(256)
void fused_prep(const float* __restrict__ w0, const float* __restrict__ w1,
                const float* __restrict__ w2, const float* __restrict__ w3,
                const float* __restrict__ w4, const float* __restrict__ w5,
                __nv_bfloat16* __restrict__ hi, __nv_bfloat16* __restrict__ lo,
                const float* __restrict__ x, const float* __restrict__ We,
                const float* __restrict__ be, float* __restrict__ h,
                int* __restrict__ counts) {
    int bid = blockIdx.x;
    int tid = threadIdx.x;
    if (bid < PREP_BLKS) {
        int i = bid * 256 + tid;
        if (i >= 622592) return;
        const float* W;
        int off, K, N;
        if (i < 32768)       { W = w0; off = 0;      K = 128; N = 256; }
        else if (i < 98304)  { W = w1; off = 32768;  K = 256; N = 256; }
        else if (i < 163840) { W = w2; off = 98304;  K = 256; N = 256; }
        else if (i < 229376) { W = w3; off = 163840; K = 256; N = 256; }
        else if (i < 360448) { W = w4; off = 229376; K = 256; N = 512; }
        else                 { W = w5; off = 360448; K = 512; N = 512; }
        int j = i - off;
        int k = j / N, n = j % N;
        float v = W[j];
        __nv_bfloat16 hh = __float2bfloat16(v);
        float r = v - __bfloat162float(hh);
        hi[(size_t)off + (size_t)n * K + k] = hh;
        lo[(size_t)off + (size_t)n * K + k] = __float2bfloat16(r);
    } else if (bid < PREP_BLKS + EMB_BLKS) {
        __shared__ float Ws[40 * 128];
        __shared__ float xs[32 * 40];
        __shared__ float bs[128];
        int n0 = (bid - PREP_BLKS) * 32;
        for (int i = tid; i < 40 * 128; i += 256) Ws[i] = We[i];
        if (tid < 128) bs[tid] = be[tid];
        for (int i = tid; i < 32 * 40; i += 256) {
            int n = n0 + (i / 40);
            xs[i] = (n < N_NODES) ? x[(size_t)n * 40 + (i % 40)] : 0.f;
        }
        __syncthreads();
        for (int i = tid; i < 32 * 128; i += 256) {
            int nl = i >> 7, col = i & 127;
            int n = n0 + nl;
            if (n >= N_NODES) continue;
            float acc = bs[col];
#pragma unroll
            for (int k = 0; k < 40; k++)
                acc = fmaf(xs[nl * 40 + k], Ws[k * 128 + col], acc);
            h[(size_t)n * 128 + col] = acc;
        }
    } else {
        int i = (bid - PREP_BLKS - EMB_BLKS) * 256 + tid;
        if (i < N_NODES) counts[i] = 0;
    }
}

// ---------------- CSR build ----------------
__global__ void hist_kernel(const int* __restrict__ ei, int* __restrict__ counts) {
    int e = blockIdx.x * blockDim.x + threadIdx.x;
    if (e >= N_EDGES) return;
    atomicAdd(&counts[ei[N_EDGES + e]], 1);
}

__global__ void scan1_kernel(const int* __restrict__ counts, int* __restrict__ off,
                             int* __restrict__ bsum) {
    int t = threadIdx.x;
    int idx = blockIdx.x * 256 + t;
    int c = (idx < N_NODES) ? counts[idx] : 0;
    int v = c;
#pragma unroll
    for (int o = 1; o < 32; o <<= 1) {
        int u = __shfl_up_sync(0xffffffffu, v, o);
        if ((t & 31) >= o) v += u;
    }
    __shared__ int ws[8];
    if ((t & 31) == 31) ws[t >> 5] = v;
    __syncthreads();
    if (t < 8) {
        int wv = ws[t];
#pragma unroll
        for (int o = 1; o < 8; o <<= 1) {
            int u = __shfl_up_sync(0xffu, wv, o);
            if (t >= o) wv += u;
        }
        ws[t] = wv;
    }
    __syncthreads();
    int base = (t >= 32) ? ws[(t >> 5) - 1] : 0;
    int inc = v + base;
    if (idx < N_NODES) off[idx] = inc - c;
    if (t == 255) bsum[blockIdx.x] = inc;
}

__global__ void scan2_kernel(int* __restrict__ off, const int* __restrict__ bsum,
                             int* __restrict__ cursor, int nblk) {
    __shared__ int sp[256];
    int t = threadIdx.x;
    int s = 0;
    for (int j = t; j < nblk; j += 256)
        if (j < (int)blockIdx.x) s += bsum[j];
    sp[t] = s;
    __syncthreads();
#pragma unroll
    for (int o = 128; o > 0; o >>= 1) {
        if (t < o) sp[t] += sp[t + o];
        __syncthreads();
    }
    int prefix = sp[0];
    int idx = blockIdx.x * 256 + t;
    if (idx < N_NODES) {
        int v = off[idx] + prefix;
        off[idx] = v;
        cursor[idx] = v;
    }
}

__global__ void fill_kernel(const int* __restrict__ ei, int* __restrict__ cursor,
                            int* __restrict__ esrc) {
    int e = blockIdx.x * blockDim.x + threadIdx.x;
    if (e >= N_EDGES) return;
    int s = ei[e];
    int d = ei[N_EDGES + e];
    int slot = atomicAdd(&cursor[d], 1);
    esrc[slot] = s;
}

// ---------------- agg + pack: z = (1+eps)*h[n] + sum h[src], packed hi/lo ----
template <int LPN>
__global__ __launch_bounds__(256)
void agg_pack(const int* __restrict__ off, const int* __restrict__ cur,
              const int* __restrict__ esrc, const float* __restrict__ h,
              const float* __restrict__ eps, int l, uint4* __restrict__ zp) {
    const int D = LPN * 8;
    int nid = blockIdx.x * (256 / LPN) + threadIdx.x / LPN;
    int gl = threadIdx.x % LPN;
    if (nid >= N_NODES) return;
    float sc = 1.f + eps[l];
    const float4* hp = (const float4*)(h + (size_t)nid * D) + gl * 2;
    float4 a = hp[0], b = hp[1];
    a.x *= sc; a.y *= sc; a.z *= sc; a.w *= sc;
    b.x *= sc; b.y *= sc; b.z *= sc; b.w *= sc;
    int s = off[nid], e = cur[nid];
    int r = (s < e) ? esrc[s] : 0;
    for (int i = s; i < e; i++) {
        int rn = (i + 1 < e) ? esrc[i + 1] : 0;
        const float4* q = (const float4*)(h + (size_t)r * D) + gl * 2;
        float4 u = q[0], v = q[1];
        r = rn;
        a.x += u.x; a.y += u.y; a.z += u.z; a.w += u.w;
        b.x += v.x; b.y += v.y; b.z += v.z; b.w += v.w;
    }
    uint4 hi, lo;
    split2(a.x, a.y, hi.x, lo.x);
    split2(a.z, a.w, hi.y, lo.y);
    split2(b.x, b.y, hi.z, lo.z);
    split2(b.z, b.w, hi.w, lo.w);
    size_t base = (size_t)nid * (D / 4) + gl * 2;
    __stcs(&zp[base], hi);
    __stcs(&zp[base + 1], lo);
}

// ---------------- HMMA bf16x3 GEMM (pure cp.async A, packed) ----------------
// BM=128, BN=128, BK=32, 128 threads, 2x2 warps, warp tile 64x64, 3-stage,
// 2 CTAs/SM.  S = K/32 is a compile-time template param (full unroll).
#define STG_A 0
#define STG_B_HI 16384
#define STG_B_LO 24576
#define STG_SIZE 32768
#define GEMM_SMEM (3 * STG_SIZE)

template <int OMODE, int S>   // OMODE 0: C fp32; 1: Cp packed hi/lo.  K = 32*S.
__global__ __launch_bounds__(128, 2)
void mma_gemm(const char* __restrict__ Ab, const __nv_bfloat16* __restrict__ Bhi,
              const __nv_bfloat16* __restrict__ Blo, const float* __restrict__ bias,
              float* __restrict__ C, char* __restrict__ Cp,
              int M, int N, int relu) {
    constexpr int K = S * 32;
    extern __shared__ char smem[];
    const int tid = threadIdx.x;
    const int lane = tid & 31;
    const int w = tid >> 5;              // 0..3
    const int wm = w & 1, wn = w >> 1;   // 2 x 2 warp grid, tile 64x64
    const int bm = blockIdx.y * 128;
    const int bn = blockIdx.x * 128;
    const uint32_t sbase = smem_u32(smem);

    float acc[4][8][4];
#pragma unroll
    for (int i = 0; i < 4; i++)
#pragma unroll
        for (int j = 0; j < 8; j++)
#pragma unroll
            for (int q = 0; q < 4; q++) acc[i][j][q] = 0.f;

#define CP_STAGE(st, k0)                                                      \
    {                                                                         \
        uint32_t sa_ = sbase + (st) * STG_SIZE + STG_A;                       \
        uint32_t sb_ = sbase + (st) * STG_SIZE;                               \
        _Pragma("unroll")                                                     \
        for (int j_ = 0; j_ < 8; j_++) {                                      \
            int idx_ = tid + j_ * 128;                                        \
            int rr_ = idx_ >> 3, q_ = idx_ & 7;                               \
            size_t go_ = (size_t)(bm + rr_) * K * 4 + (size_t)(k0) * 4 +      \
                         (q_ >> 1) * 32 + (q_ & 1) * 16;                      \
            uint32_t so_ = (uint32_t)(rr_ * 128 + ((q_ ^ (rr_ & 7)) << 4));   \
            CP16(sa_ + so_, Ab + go_);                                        \
        }                                                                     \
        _Pragma("unroll")                                                     \
        for (int j_ = 0; j_ < 4; j_++) {                                      \
            int idx_ = tid + j_ * 128;                                        \
            int n_ = idx_ >> 2, g_ = idx_ & 3;                                \
            size_t go_ = (size_t)(bn + n_) * K + (k0) + g_ * 8;               \
            uint32_t so_ = SWZ(n_, g_);                                       \
            CP16(sb_ + STG_B_HI + so_, Bhi + go_);                            \
            CP16(sb_ + STG_B_LO + so_, Blo + go_);                            \
        }                                                                     \
        asm volatile("cp.async.commit_group;" ::: "memory");                  \
    }

    CP_STAGE(0, 0);
    CP_STAGE(1, 32);
    asm volatile("cp.async.wait_group 1;" ::: "memory");
    __syncthreads();

    uint32_t a_row128[4], a_rkey[4];
#pragma unroll
    for (int mt = 0; mt < 4; mt++) {
        int row = wm * 64 + mt * 16 + (lane & 15);
        a_row128[mt] = (uint32_t)(row * 128);
        a_rkey[mt] = (uint32_t)(row & 7);
    }
    const uint32_t a_kbit = (lane >> 4) & 1;
    uint32_t b_base[4], b_key[4];
#pragma unroll
    for (int np = 0; np < 4; np++) {
        int row = wn * 64 + np * 16 + ((lane >> 4) & 1) * 8 + (lane & 7);
        b_base[np] = (uint32_t)(row * 64);
        b_key[np] = (uint32_t)((row >> 1) & 3);
    }
    const uint32_t b_c16_bit = (lane >> 3) & 1;

#pragma unroll
    for (int s = 0; s < S; s++) {
        const int cst = s % 3;
        if (s + 2 < S) CP_STAGE((s + 2) % 3, (s + 2) << 5);

        const uint32_t sg = sbase + cst * STG_SIZE;
#pragma unroll
        for (int kh = 0; kh < 2; kh++) {
            uint32_t ahi[4][4], alo[4][4];
#pragma unroll
            for (int mt = 0; mt < 4; mt++) {
                uint32_t q = (uint32_t)(kh * 2 + a_kbit) * 2;
                uint32_t base = sg + STG_A + a_row128[mt];
                LDM4(ahi[mt], base + ((q ^ a_rkey[mt]) << 4));
                LDM4(alo[mt], base + (((q + 1) ^ a_rkey[mt]) << 4));
            }
#pragma unroll
            for (int np = 0; np < 4; np++) {
                uint32_t c16 = (uint32_t)(kh * 2) + b_c16_bit;
                uint32_t bd = sg + b_base[np] + ((c16 ^ b_key[np]) << 4);
                uint32_t bh[4], bl[4];
                LDM4(bh, bd + STG_B_HI);
                LDM4(bl, bd + STG_B_LO);
#pragma unroll
                for (int mt = 0; mt < 4; mt++) {
                    MMA16816(acc[mt][np * 2], ahi[mt], bh[0], bh[1]);
                    MMA16816(acc[mt][np * 2], ahi[mt], bl[0], bl[1]);
                    MMA16816(acc[mt][np * 2], alo[mt], bh[0], bh[1]);
                    MMA16816(acc[mt][np * 2 + 1], ahi[mt], bh[2], bh[3]);
                    MMA16816(acc[mt][np * 2 + 1], ahi[mt], bl[2], bl[3]);
                    MMA16816(acc[mt][np * 2 + 1], alo[mt], bh[2], bh[3]);
                }
            }
        }

        if (s + 1 < S) {
            if (s + 2 < S) {
                asm volatile("cp.async.wait_group 1;" ::: "memory");
            } else {
                asm volatile("cp.async.wait_group 0;" ::: "memory");
            }
            __syncthreads();
        }
    }

    // ---- epilogue ----
#pragma unroll
    for (int mt = 0; mt < 4; mt++) {
        int r0 = bm + wm * 64 + mt * 16 + (lane >> 2);
#pragma unroll
        for (int nt = 0; nt < 8; nt++) {
            int col = bn + wn * 64 + nt * 8 + (lane & 3) * 2;
            float b0 = bias[col], b1 = bias[col + 1];
            float v0 = acc[mt][nt][0] + b0, v1 = acc[mt][nt][1] + b1;
            float v2 = acc[mt][nt][2] + b0, v3 = acc[mt][nt][3] + b1;
            if (relu) {
                v0 = fmaxf(v0, 0.f); v1 = fmaxf(v1, 0.f);
                v2 = fmaxf(v2, 0.f); v3 = fmaxf(v3, 0.f);
            }
            if (OMODE == 0) {
                if (r0 < M) *(float2*)(C + (size_t)r0 * N + col) = make_float2(v0, v1);
                if (r0 + 8 < M) *(float2*)(C + (size_t)(r0 + 8) * N + col) = make_float2(v2, v3);
            } else {
                uint32_t h01, l01, h23, l23;
                split2(v0, v1, h01, l01);
                split2(v2, v3, h23, l23);
                size_t base = (size_t)r0 * N * 4 + (size_t)(col >> 3) * 32 +
                              (col & 7) * 2;
                if (r0 < M) {
                    *(uint32_t*)(Cp + base) = h01;
                    *(uint32_t*)(Cp + base + 16) = l01;
                }
                if (r0 + 8 < M) {
                    size_t b2_ = base + (size_t)8 * N * 4;
                    *(uint32_t*)(Cp + b2_) = h23;
                    *(uint32_t*)(Cp + b2_ + 16) = l23;
                }
            }
        }
    }
#undef CP_STAGE
}

// ---------------- fused pool + task head (batch is sorted) ----------------
__device__ __forceinline__ int lowb(const int* __restrict__ a, int n, int v) {
    int lo = 0, hi = n;
    while (lo < hi) {
        int m = (lo + hi) >> 1;
        if (a[m] < v) lo = m + 1; else hi = m;
    }
    return lo;
}

__global__ __launch_bounds__(128)
void pool_task_kernel(const int* __restrict__ batch, const float* __restrict__ h,
                      const float* __restrict__ W, const float* __restrict__ b,
                      float* __restrict__ out) {
    int g = blockIdx.x;
    int t = threadIdx.x;
    int start = lowb(batch, N_NODES, g);
    int end = lowb(batch, N_NODES, g + 1);
    float4 acc = make_float4(0.f, 0.f, 0.f, 0.f);
    for (int n = start; n < end; n++) {
        float4 v = ((const float4*)(h + (size_t)n * 512))[t];
        acc.x += v.x; acc.y += v.y; acc.z += v.z; acc.w += v.w;
    }
    float4 wv = ((const float4*)W)[t];
    float d = acc.x * wv.x + acc.y * wv.y + acc.z * wv.z + acc.w * wv.w;
#pragma unroll
    for (int o = 16; o > 0; o >>= 1) d += __shfl_xor_sync(0xffffffffu, d, o);
    __shared__ float s[4];
    if ((t & 31) == 0) s[t >> 5] = d;
    __syncthreads();
    if (t == 0) out[g] = s[0] + s[1] + s[2] + s[3] + b[0];
}

// ---------------- launch ----------------
extern "C" void kernel_launch(void* const* d_in, const int* in_sizes, int n_in,
                              void* d_out, int out_size) {
    const float* x       = (const float*)d_in[0];
    const int*   ei      = (const int*)d_in[1];
    const int*   batch   = (const int*)d_in[2];
    const float* W_embed = (const float*)d_in[3];
    const float* b_embed = (const float*)d_in[4];
    const float* eps     = (const float*)d_in[5];
    const float* W1[3] = {(const float*)d_in[6],  (const float*)d_in[10], (const float*)d_in[14]};
    const float* b1[3] = {(const float*)d_in[7],  (const float*)d_in[11], (const float*)d_in[15]};
    const float* W2[3] = {(const float*)d_in[8],  (const float*)d_in[12], (const float*)d_in[16]};
    const float* b2[3] = {(const float*)d_in[9],  (const float*)d_in[13], (const float*)d_in[17]};
    const float* W_task = (const float*)d_in[18];
    const float* b_task = (const float*)d_in[19];
    float* out = (float*)d_out;

    float *h;
    uint32_t *zp, *tp;
    __nv_bfloat16 *whi, *wlo;
    int *counts, *off, *cur, *bsum, *esrc;
    cudaGetSymbolAddress((void**)&h, g_h);
    cudaGetSymbolAddress((void**)&zp, g_zp);
    cudaGetSymbolAddress((void**)&tp, g_tp);
    cudaGetSymbolAddress((void**)&whi, g_whi);
    cudaGetSymbolAddress((void**)&wlo, g_wlo);
    cudaGetSymbolAddress((void**)&counts, g_counts);
    cudaGetSymbolAddress((void**)&off, g_off);
    cudaGetSymbolAddress((void**)&cur, g_cur);
    cudaGetSymbolAddress((void**)&bsum, g_bsum);
    cudaGetSymbolAddress((void**)&esrc, g_esrc);

    cudaFuncSetAttribute(mma_gemm<1, 4>, cudaFuncAttributeMaxDynamicSharedMemorySize, GEMM_SMEM);
    cudaFuncSetAttribute(mma_gemm<1, 8>, cudaFuncAttributeMaxDynamicSharedMemorySize, GEMM_SMEM);
    cudaFuncSetAttribute(mma_gemm<0, 8>, cudaFuncAttributeMaxDynamicSharedMemorySize, GEMM_SMEM);
    cudaFuncSetAttribute(mma_gemm<0, 16>, cudaFuncAttributeMaxDynamicSharedMemorySize, GEMM_SMEM);

    fused_prep<<<PREP_BLKS + EMB_BLKS + ZERO_BLKS, 256>>>(
        W1[0], W2[0], W1[1], W2[1], W1[2], W2[2], whi, wlo,
        x, W_embed, b_embed, h, counts);

    const int NBLK = (N_NODES + 255) / 256;   // 391
    hist_kernel<<<(N_EDGES + 255) / 256, 256>>>(ei, counts);
    scan1_kernel<<<NBLK, 256>>>(counts, off, bsum);
    scan2_kernel<<<NBLK, 256>>>(off, bsum, cur, NBLK);
    fill_kernel<<<(N_EDGES + 255) / 256, 256>>>(ei, cur, esrc);

    const size_t woff[6] = {0, 32768, 98304, 163840, 229376, 360448};
    const int MT = M_PAD / 128;   // 782

    for (int l = 0; l < 3; l++) {
        // aggregation into packed z
        if (l == 0)
            agg_pack<16><<<(N_NODES + 15) / 16, 256>>>(off, cur, esrc, h, eps, l,
                                                       (uint4*)zp);
        else
            agg_pack<32><<<(N_NODES + 7) / 8, 256>>>(off, cur, esrc, h, eps, l,
                                                     (uint4*)zp);

        // GEMM1: packed z -> packed t, relu
        if (l == 0)
            mma_gemm<1, 4><<<dim3(2, MT), 128, GEMM_SMEM>>>(
                (const char*)zp, whi + woff[0], wlo + woff[0], b1[0],
                nullptr, (char*)tp, N_NODES, 256, 1);
        else if (l == 1)
            mma_gemm<1, 8><<<dim3(2, MT), 128, GEMM_SMEM>>>(
                (const char*)zp, whi + woff[2], wlo + woff[2], b1[1],
                nullptr, (char*)tp, N_NODES, 256, 1);
        else
            mma_gemm<1, 8><<<dim3(4, MT), 128, GEMM_SMEM>>>(
                (const char*)zp, whi + woff[4], wlo + woff[4], b1[2],
                nullptr, (char*)tp, N_NODES, 512, 1);

        // GEMM2: packed t -> h fp32, relu unless last
        if (l == 0)
            mma_gemm<0, 8><<<dim3(2, MT), 128, GEMM_SMEM>>>(
                (const char*)tp, whi + woff[1], wlo + woff[1], b2[0],
                h, nullptr, N_NODES, 256, 1);
        else if (l == 1)
            mma_gemm<0, 8><<<dim3(2, MT), 128, GEMM_SMEM>>>(
                (const char*)tp, whi + woff[3], wlo + woff[3], b2[1],
                h, nullptr, N_NODES, 256, 1);
        else
            mma_gemm<0, 16><<<dim3(4, MT), 128, GEMM_SMEM>>>(
                (const char*)tp, whi + woff[5], wlo + woff[5], b2[2],
                h, nullptr, N_NODES, 512, 0);
    }

    pool_task_kernel<<<N_GRAPHS, 128>>>(batch, h, W_task, b_task, out);
}